// round 1
// baseline (speedup 1.0000x reference)
#include <cuda_runtime.h>
#include <math.h>

// ---------------------------------------------------------------------------
// Fused 3-layer GCN on the fixed 21-node hand-skeleton graph, 50000 graphs.
//
// Key structural facts baked in at compile time:
//   deg (incl self-loop): node0=1, nodes1..20=2  -> dinv0=1, dinv=1/sqrt(2)
//   mix:  m[n] = c_self[n]*z[n] + c_par[n]*z[par[n]]   (n=0: m = z[0])
//   pool+layer3 collapse: pooled = (sum_n w[n]*h2[n]) @ W3 / 21 + b3
// BN folded:  bn(m + b) = m*s + t,  s = g*rsqrt(v+eps), t = (b-mean)*s + beta
// ---------------------------------------------------------------------------

#define NODES       21
#define NUM_GRAPHS  50000
#define H1DIM       64
#define H2DIM       128
#define NCLS        29
#define GPB         16            // graphs per block (2 groups x 8 iters)
#define NBLOCKS     (NUM_GRAPHS / GPB)   // 3125

#define R2 0.70710678118654752440f

__constant__ int   c_par[NODES] = {0,0,1,2,3, 0,5,6,7, 0,9,10,11, 0,13,14,15, 0,17,18,19};
__constant__ float c_cp [NODES] = {0.f, R2,0.5f,0.5f,0.5f, R2,0.5f,0.5f,0.5f,
                                   R2,0.5f,0.5f,0.5f, R2,0.5f,0.5f,0.5f, R2,0.5f,0.5f,0.5f};
__constant__ float c_w  [NODES] = {4.535533905932737f,
                                   1.f,1.f,1.f,0.5f, 1.f,1.f,1.f,0.5f,
                                   1.f,1.f,1.f,0.5f, 1.f,1.f,1.f,0.5f, 1.f,1.f,1.f,0.5f};

// packed f32x2 FMA: d = a*b + d  (elementwise on two packed fp32 lanes)
__device__ __forceinline__ void ffma2(unsigned long long& d,
                                      unsigned long long a,
                                      unsigned long long b) {
    asm("fma.rn.f32x2 %0, %1, %2, %0;" : "+l"(d) : "l"(a), "l"(b));
}

// ---- dynamic shared memory layout (float offsets) -------------------------
#define SM_W1    0                 // 192   : W1 [3][64]
#define SM_S1    (SM_W1 + 192)     // 64
#define SM_T1    (SM_S1 + 64)      // 64
#define SM_S2    (SM_T1 + 64)      // 128
#define SM_T2    (SM_S2 + 128)     // 128
#define SM_B3    (SM_T2 + 128)     // 32
#define SM_X     (SM_B3 + 32)      // 2*64  : x per group [21*3]
#define SM_V     (SM_X + 128)      // 2*128 : v vector per group
#define SM_W3    (SM_V + 256)      // 3712  : W3 [128][29]
#define SM_Z1    (SM_W3 + 3712)    // 2*1344: z1 per group [21][64]
#define SM_H1    (SM_Z1 + 2688)    // 2*1344: h1 per group [21][64]
#define SM_W2Q   (SM_H1 + 2688)    // 8192  : W2 repacked [16][128] float4 (k-quads)
#define SM_TOTAL (SM_W2Q + 8192)   // 18272 floats = 73088 bytes
// SM_W2Q*4 = 40320 bytes, 16B aligned; SM_H1*4 also 16B aligned.

__global__ void __launch_bounds__(256, 3)
gcn_fused_kernel(const float* __restrict__ x,
                 const float* __restrict__ W1, const float* __restrict__ b1,
                 const float* __restrict__ g1, const float* __restrict__ be1,
                 const float* __restrict__ m1, const float* __restrict__ v1,
                 const float* __restrict__ W2, const float* __restrict__ b2,
                 const float* __restrict__ g2, const float* __restrict__ be2,
                 const float* __restrict__ m2, const float* __restrict__ v2,
                 const float* __restrict__ W3, const float* __restrict__ b3,
                 float* __restrict__ out) {
    extern __shared__ float sm[];
    const int tid    = threadIdx.x;          // 0..255
    const int group  = tid >> 7;             // 0 or 1
    const int wg_tid = tid & 127;            // thread within group

    // ---------------- stage weights / folded BN (once per block) ----------
    for (int i = tid; i < 192; i += 256) sm[SM_W1 + i] = W1[i];
    if (tid < 64) {
        float s = g1[tid] * rsqrtf(v1[tid] + 1e-5f);
        sm[SM_S1 + tid] = s;
        sm[SM_T1 + tid] = (b1[tid] - m1[tid]) * s + be1[tid];
    }
    if (tid < 128) {
        float s = g2[tid] * rsqrtf(v2[tid] + 1e-5f);
        sm[SM_S2 + tid] = s;
        sm[SM_T2 + tid] = (b2[tid] - m2[tid]) * s + be2[tid];
    }
    if (tid < NCLS) sm[SM_B3 + tid] = b3[tid];
    for (int i = tid; i < 128 * NCLS; i += 256) sm[SM_W3 + i] = W3[i];
    // repack W2 [64][128] -> k-quad float4s: W2q[kq][j] = (W2[4kq][j],...,W2[4kq+3][j])
    for (int i = tid; i < 64 * 128; i += 256) {
        int k = i >> 7, j = i & 127;
        sm[SM_W2Q + (((k >> 2) * 128 + j) << 2) + (k & 3)] = W2[i];
    }
    __syncthreads();

    float* const xg  = sm + SM_X  + group * 64;
    float* const z1g = sm + SM_Z1 + group * (NODES * 64);
    float* const h1g = sm + SM_H1 + group * (NODES * 64);
    float* const vg  = sm + SM_V  + group * 128;

    const int k  = wg_tid & 63;   // layer-1 column
    const int ng = wg_tid >> 6;   // layer-1 row parity

    for (int it = 0; it < GPB / 2; ++it) {
        const int g = blockIdx.x * GPB + group * (GPB / 2) + it;

        // -------- load x for this graph (63 floats) ------------------------
        if (wg_tid < NODES * 3) xg[wg_tid] = x[(size_t)g * (NODES * 3) + wg_tid];
        __syncthreads();

        // -------- layer 1: z1 = x @ W1 -------------------------------------
        {
            const float w1a = sm[SM_W1 +       k];
            const float w1b = sm[SM_W1 +  64 + k];
            const float w1c = sm[SM_W1 + 128 + k];
            #pragma unroll
            for (int n = ng; n < NODES; n += 2) {
                float z = fmaf(xg[n * 3], w1a,
                          fmaf(xg[n * 3 + 1], w1b, xg[n * 3 + 2] * w1c));
                z1g[n * 64 + k] = z;
            }
        }
        __syncthreads();

        // -------- layer 1: mix + folded BN + ReLU --------------------------
        {
            const float s1k = sm[SM_S1 + k];
            const float t1k = sm[SM_T1 + k];
            #pragma unroll
            for (int n = ng; n < NODES; n += 2) {
                float zz = z1g[n * 64 + k];
                float mm = (n == 0) ? zz
                         : fmaf(0.5f, zz, c_cp[n] * z1g[c_par[n] * 64 + k]);
                h1g[n * 64 + k] = fmaxf(fmaf(mm, s1k, t1k), 0.f);
            }
        }
        __syncthreads();

        // -------- layer 2 hot loop: z2[:,j] = h1 @ W2[:,j] (packed f32x2) --
        {
            unsigned long long acc[NODES];
            #pragma unroll
            for (int n = 0; n < NODES; ++n) acc[n] = 0ull;

            const ulonglong2* __restrict__ w2q =
                reinterpret_cast<const ulonglong2*>(sm + SM_W2Q);
            #pragma unroll 4
            for (int kq = 0; kq < 16; ++kq) {
                ulonglong2 wv = w2q[kq * 128 + wg_tid];      // LDS.128
                #pragma unroll
                for (int n = 0; n < NODES; ++n) {
                    ulonglong2 hv = *reinterpret_cast<const ulonglong2*>(
                        h1g + n * 64 + (kq << 2));           // LDS.128 broadcast
                    ffma2(acc[n], hv.x, wv.x);
                    ffma2(acc[n], hv.y, wv.y);
                }
            }

            // epilogue: horizontal add, mix, BN+ReLU, weighted pool -> v[j]
            float z[NODES];
            #pragma unroll
            for (int n = 0; n < NODES; ++n) {
                float2 f = *reinterpret_cast<float2*>(&acc[n]);
                z[n] = f.x + f.y;
            }
            const float sj = sm[SM_S2 + wg_tid];
            const float tj = sm[SM_T2 + wg_tid];
            float vacc = c_w[0] * fmaxf(fmaf(z[0], sj, tj), 0.f);
            #pragma unroll
            for (int n = 1; n < NODES; ++n) {
                float mm = fmaf(0.5f, z[n], c_cp[n] * z[c_par[n]]);
                vacc = fmaf(c_w[n], fmaxf(fmaf(mm, sj, tj), 0.f), vacc);
            }
            vg[wg_tid] = vacc;
        }
        __syncthreads();

        // -------- layer 3 + log_softmax (warp 0 of each group) -------------
        if (wg_tid < 32) {
            const int c = wg_tid;
            float y = -1e30f;
            if (c < NCLS) {
                float a3 = 0.f;
                #pragma unroll 8
                for (int j = 0; j < 128; ++j)
                    a3 = fmaf(vg[j], sm[SM_W3 + j * NCLS + c], a3);
                y = fmaf(a3, 1.f / 21.f, sm[SM_B3 + c]);
            }
            float mx = y;
            #pragma unroll
            for (int o = 16; o; o >>= 1)
                mx = fmaxf(mx, __shfl_xor_sync(0xffffffffu, mx, o));
            float e = (c < NCLS) ? expf(y - mx) : 0.f;
            float s = e;
            #pragma unroll
            for (int o = 16; o; o >>= 1)
                s += __shfl_xor_sync(0xffffffffu, s, o);
            if (c < NCLS)
                out[(size_t)g * NCLS + c] = y - mx - logf(s);
        }
        __syncthreads();   // protect xg/z1g/h1g/vg for next iteration
    }
}

extern "C" void kernel_launch(void* const* d_in, const int* in_sizes, int n_in,
                              void* d_out, int out_size) {
    const float* x   = (const float*)d_in[0];
    const float* W1  = (const float*)d_in[1];
    const float* b1  = (const float*)d_in[2];
    const float* g1  = (const float*)d_in[3];
    const float* be1 = (const float*)d_in[4];
    const float* m1  = (const float*)d_in[5];
    const float* v1  = (const float*)d_in[6];
    const float* W2  = (const float*)d_in[7];
    const float* b2  = (const float*)d_in[8];
    const float* g2  = (const float*)d_in[9];
    const float* be2 = (const float*)d_in[10];
    const float* m2  = (const float*)d_in[11];
    const float* v2  = (const float*)d_in[12];
    const float* W3  = (const float*)d_in[13];
    const float* b3  = (const float*)d_in[14];
    // d_in[15] edge_index, d_in[16] batch: structure is compile-time known.

    const int smem_bytes = SM_TOTAL * (int)sizeof(float);   // 73088
    cudaFuncSetAttribute(gcn_fused_kernel,
                         cudaFuncAttributeMaxDynamicSharedMemorySize, smem_bytes);
    gcn_fused_kernel<<<NBLOCKS, 256, smem_bytes>>>(
        x, W1, b1, g1, be1, m1, v1,
        W2, b2, g2, be2, m2, v2, W3, b3, (float*)d_out);
}

// round 2
// speedup vs baseline: 1.6207x; 1.6207x over previous
#include <cuda_runtime.h>
#include <math.h>

// ---------------------------------------------------------------------------
// Fused 3-layer GCN, fixed 21-node hand skeleton, 50000 graphs.
// R2: FMA-bound layer-2 layout. Each graph handled by a 2-warp "pair":
//   warp A: nodes 0..10, warp B: nodes 11..20; each thread owns 4 j-columns
//   (lane, lane+32, lane+64, lane+96) with k-packed f32x2 accumulators.
//   wf/FFMA2 = 2/11 + 1/4 = 0.43 < 0.5  ->  FMA pipe binds, not LDS.
// Pair-scoped named barriers; constexpr graph tables (compile-time folded).
// ---------------------------------------------------------------------------

#define NODES       21
#define NUM_GRAPHS  50000
#define NCLS        29
#define GPB         8
#define NBLOCKS     (NUM_GRAPHS / GPB)   // 6250
#define R2C         0.70710678118654752440f

__device__ constexpr int   PAR[NODES] = {0,0,1,2,3, 0,5,6,7, 0,9,10,11, 0,13,14,15, 0,17,18,19};
__device__ constexpr float CP [NODES] = {0.f,R2C,.5f,.5f,.5f, R2C,.5f,.5f,.5f,
                                         R2C,.5f,.5f,.5f, R2C,.5f,.5f,.5f, R2C,.5f,.5f,.5f};
__device__ constexpr float WN [NODES] = {4.535533905932737f,
                                         1.f,1.f,1.f,.5f, 1.f,1.f,1.f,.5f,
                                         1.f,1.f,1.f,.5f, 1.f,1.f,1.f,.5f, 1.f,1.f,1.f,.5f};

// packed f32x2 FMA: d = a*b + d
__device__ __forceinline__ void ffma2(unsigned long long& d,
                                      unsigned long long a,
                                      unsigned long long b) {
    asm("fma.rn.f32x2 %0, %1, %2, %0;" : "+l"(d) : "l"(a), "l"(b));
}

__device__ __forceinline__ void barp(int id) {   // pair barrier: 64 threads
    asm volatile("bar.sync %0, 64;" :: "r"(id) : "memory");
}

// ---- shared memory layout (float offsets) ---------------------------------
#define SM_W1    0                  // 192 : W1 [3][64]
#define SM_S1    192                // 64
#define SM_T1    256                // 64
#define SM_S2    320                // 128
#define SM_T2    448                // 128
#define SM_B3    576                // 32
#define SM_W3Q   608                // 3712 : W3 repacked [32 jq][29 c] float4
#define SM_W2Q   4320               // 8192 : W2 repacked [16 kq][128 j] float4
#define SM_PAIR  12512              // 4 pairs x 1952 floats
#define P_X      0                  // 96   : x padded [21][4]
#define P_H1     96                 // 1344 : h1 [21][64]
#define P_CR     1440               // 256  : cross z2[0], z2[10] (128 each)
#define P_VA     1696               // 128  : warp-A partial pool
#define P_VF     1824               // 128  : full pooled vector
#define PAIR_STRIDE 1952
#define SM_TOTAL (SM_PAIR + 4 * PAIR_STRIDE)   // 20320 floats = 81280 bytes

// Layer-2 GEMM tile: nodes [NBASE, NBASE+NN), 4 j-columns per lane, k-packed.
template<int NBASE, int NN>
__device__ __forceinline__ void gemm2(const float* __restrict__ sm,
                                      const float* __restrict__ PH,
                                      int lane, float (&z)[NN][4]) {
    unsigned long long acc[NN][4];
    #pragma unroll
    for (int i = 0; i < NN; ++i)
        #pragma unroll
        for (int c = 0; c < 4; ++c) acc[i][c] = 0ull;

    #pragma unroll 1
    for (int kq = 0; kq < 16; ++kq) {
        const ulonglong2* __restrict__ w2 =
            reinterpret_cast<const ulonglong2*>(sm + SM_W2Q) + kq * 128 + lane;
        const ulonglong2 wv0 = w2[0];
        const ulonglong2 wv1 = w2[32];
        const ulonglong2 wv2 = w2[64];
        const ulonglong2 wv3 = w2[96];
        #pragma unroll
        for (int i = 0; i < NN; ++i) {
            const ulonglong2 hv = *reinterpret_cast<const ulonglong2*>(
                PH + (NBASE + i) * 64 + kq * 4);            // broadcast
            ffma2(acc[i][0], hv.x, wv0.x); ffma2(acc[i][0], hv.y, wv0.y);
            ffma2(acc[i][1], hv.x, wv1.x); ffma2(acc[i][1], hv.y, wv1.y);
            ffma2(acc[i][2], hv.x, wv2.x); ffma2(acc[i][2], hv.y, wv2.y);
            ffma2(acc[i][3], hv.x, wv3.x); ffma2(acc[i][3], hv.y, wv3.y);
        }
    }
    #pragma unroll
    for (int i = 0; i < NN; ++i)
        #pragma unroll
        for (int c = 0; c < 4; ++c) {
            float2 f = *reinterpret_cast<float2*>(&acc[i][c]);
            z[i][c] = f.x + f.y;
        }
}

__global__ void __launch_bounds__(256, 2)
gcn_fused_kernel(const float* __restrict__ x,
                 const float* __restrict__ W1, const float* __restrict__ b1,
                 const float* __restrict__ g1, const float* __restrict__ be1,
                 const float* __restrict__ m1, const float* __restrict__ v1,
                 const float* __restrict__ W2, const float* __restrict__ b2,
                 const float* __restrict__ g2, const float* __restrict__ be2,
                 const float* __restrict__ m2, const float* __restrict__ v2,
                 const float* __restrict__ W3, const float* __restrict__ b3,
                 float* __restrict__ out) {
    extern __shared__ float sm[];
    const int tid  = threadIdx.x;
    const int lane = tid & 31;
    const int pair = tid >> 6;          // 0..3
    const int wip  = (tid >> 5) & 1;    // 0 = warp A, 1 = warp B
    const int t64  = wip * 32 + lane;   // thread id within pair

    // ---------------- stage weights / folded BN (once per block) ----------
    for (int i = tid; i < 192; i += 256) sm[SM_W1 + i] = W1[i];
    if (tid < 64) {
        float s = g1[tid] * rsqrtf(v1[tid] + 1e-5f);
        sm[SM_S1 + tid] = s;
        sm[SM_T1 + tid] = (b1[tid] - m1[tid]) * s + be1[tid];
    }
    if (tid < 128) {
        float s = g2[tid] * rsqrtf(v2[tid] + 1e-5f);
        sm[SM_S2 + tid] = s;
        sm[SM_T2 + tid] = (b2[tid] - m2[tid]) * s + be2[tid];
    }
    if (tid < NCLS) sm[SM_B3 + tid] = b3[tid];
    // W2 repack: w2q[kq*128 + j] = float4(W2[4kq+0][j], ..., W2[4kq+3][j])
    for (int i = tid; i < 2048; i += 256) {
        int kq = i >> 7, j = i & 127;
        float4 v;
        v.x = W2[(4 * kq + 0) * 128 + j];
        v.y = W2[(4 * kq + 1) * 128 + j];
        v.z = W2[(4 * kq + 2) * 128 + j];
        v.w = W2[(4 * kq + 3) * 128 + j];
        reinterpret_cast<float4*>(sm + SM_W2Q)[i] = v;
    }
    // W3 repack: w3q[jq*29 + c] = float4(W3[4jq+0][c], ..., W3[4jq+3][c])
    for (int i = tid; i < 32 * NCLS; i += 256) {
        int jq = i / NCLS, c = i - jq * NCLS;
        float4 v;
        v.x = W3[(4 * jq + 0) * NCLS + c];
        v.y = W3[(4 * jq + 1) * NCLS + c];
        v.z = W3[(4 * jq + 2) * NCLS + c];
        v.w = W3[(4 * jq + 3) * NCLS + c];
        reinterpret_cast<float4*>(sm + SM_W3Q)[i] = v;
    }
    __syncthreads();

    float* const PB  = sm + SM_PAIR + pair * PAIR_STRIDE;
    float* const PX  = PB + P_X;
    float* const PH  = PB + P_H1;
    float* const PCR = PB + P_CR;
    float* const PVA = PB + P_VA;
    float* const PVF = PB + P_VF;
    const int barid = pair + 1;

    for (int it = 0; it < 2; ++it) {
        const int g = blockIdx.x * GPB + it * 4 + pair;

        // -------- load x (63 floats, padded [21][4]) -----------------------
        if (t64 < 63) {
            int n = t64 / 3, r = t64 - 3 * n;
            PX[4 * n + r] = x[(size_t)g * 63 + t64];
        }
        barp(barid);

        // -------- layer 1: column k = t64 ----------------------------------
        {
            const int k = t64;
            const float w1a = sm[SM_W1 + k];
            const float w1b = sm[SM_W1 + 64 + k];
            const float w1c = sm[SM_W1 + 128 + k];
            const float s1  = sm[SM_S1 + k];
            const float t1  = sm[SM_T1 + k];
            float z1[NODES];
            #pragma unroll
            for (int n = 0; n < NODES; ++n) {
                float4 xq = *reinterpret_cast<const float4*>(PX + 4 * n);
                z1[n] = fmaf(xq.x, w1a, fmaf(xq.y, w1b, xq.z * w1c));
            }
            PH[k] = fmaxf(fmaf(z1[0], s1, t1), 0.f);
            #pragma unroll
            for (int n = 1; n < NODES; ++n) {
                float mm = fmaf(0.5f, z1[n], CP[n] * z1[PAR[n]]);
                PH[n * 64 + k] = fmaxf(fmaf(mm, s1, t1), 0.f);
            }
        }
        barp(barid);

        // -------- layer 2 + epilogue ---------------------------------------
        float s2v[4], t2v[4];
        #pragma unroll
        for (int c = 0; c < 4; ++c) {
            s2v[c] = sm[SM_S2 + lane + 32 * c];
            t2v[c] = sm[SM_T2 + lane + 32 * c];
        }

        if (wip == 0) {
            // ---- warp A: nodes 0..10 (all parents local) ----
            float z[11][4];
            gemm2<0, 11>(sm, PH, lane, z);
            float va[4];
            #pragma unroll
            for (int c = 0; c < 4; ++c) {
                float h = fmaxf(fmaf(z[0][c], s2v[c], t2v[c]), 0.f);
                va[c] = WN[0] * h;
            }
            #pragma unroll
            for (int n = 1; n <= 10; ++n)
                #pragma unroll
                for (int c = 0; c < 4; ++c) {
                    float mm = fmaf(0.5f, z[n][c], CP[n] * z[PAR[n]][c]);
                    float h  = fmaxf(fmaf(mm, s2v[c], t2v[c]), 0.f);
                    va[c] = fmaf(WN[n], h, va[c]);
                }
            #pragma unroll
            for (int c = 0; c < 4; ++c) {
                int j = lane + 32 * c;
                PCR[j]       = z[0][c];     // z2[node 0]
                PCR[128 + j] = z[10][c];    // z2[node 10]
                PVA[j]       = va[c];
            }
            barp(barid);
            // warp A done for this graph
        } else {
            // ---- warp B: nodes 11..20 ----
            float z[10][4];
            gemm2<11, 10>(sm, PH, lane, z);
            barp(barid);                    // wait for A's cross + vA
            float zc0[4], zc10[4];
            #pragma unroll
            for (int c = 0; c < 4; ++c) {
                int j = lane + 32 * c;
                zc0[c]  = PCR[j];
                zc10[c] = PCR[128 + j];
            }
            float vb[4] = {0.f, 0.f, 0.f, 0.f};
            #pragma unroll
            for (int n = 11; n <= 20; ++n)
                #pragma unroll
                for (int c = 0; c < 4; ++c) {
                    float zp = (PAR[n] == 0)  ? zc0[c]
                             : (PAR[n] == 10) ? zc10[c]
                                              : z[PAR[n] - 11][c];
                    float mm = fmaf(0.5f, z[n - 11][c], CP[n] * zp);
                    float h  = fmaxf(fmaf(mm, s2v[c], t2v[c]), 0.f);
                    vb[c] = fmaf(WN[n], h, vb[c]);
                }
            #pragma unroll
            for (int c = 0; c < 4; ++c) {
                int j = lane + 32 * c;
                PVF[j] = PVA[j] + vb[c];
            }
            __syncwarp();

            // ---- layer 3 + log_softmax (warp B) ----
            float y = -1e30f;
            if (lane < NCLS) {
                float a3 = 0.f;
                #pragma unroll 1
                for (int jq = 0; jq < 32; ++jq) {
                    float4 vq = *reinterpret_cast<const float4*>(PVF + 4 * jq);
                    float4 wq = *reinterpret_cast<const float4*>(
                        sm + SM_W3Q + (jq * NCLS + lane) * 4);
                    a3 = fmaf(vq.x, wq.x, fmaf(vq.y, wq.y,
                         fmaf(vq.z, wq.z, fmaf(vq.w, wq.w, a3))));
                }
                y = fmaf(a3, 1.f / 21.f, sm[SM_B3 + lane]);
            }
            float mx = y;
            #pragma unroll
            for (int o = 16; o; o >>= 1)
                mx = fmaxf(mx, __shfl_xor_sync(0xffffffffu, mx, o));
            float e = (lane < NCLS) ? expf(y - mx) : 0.f;
            float s = e;
            #pragma unroll
            for (int o = 16; o; o >>= 1)
                s += __shfl_xor_sync(0xffffffffu, s, o);
            if (lane < NCLS)
                out[(size_t)g * NCLS + lane] = y - mx - logf(s);
        }
        // next iteration's x-store / h1-store are fenced by B1/B2 above
    }
}

extern "C" void kernel_launch(void* const* d_in, const int* in_sizes, int n_in,
                              void* d_out, int out_size) {
    const float* x   = (const float*)d_in[0];
    const float* W1  = (const float*)d_in[1];
    const float* b1  = (const float*)d_in[2];
    const float* g1  = (const float*)d_in[3];
    const float* be1 = (const float*)d_in[4];
    const float* m1  = (const float*)d_in[5];
    const float* v1  = (const float*)d_in[6];
    const float* W2  = (const float*)d_in[7];
    const float* b2  = (const float*)d_in[8];
    const float* g2  = (const float*)d_in[9];
    const float* be2 = (const float*)d_in[10];
    const float* m2  = (const float*)d_in[11];
    const float* v2  = (const float*)d_in[12];
    const float* W3  = (const float*)d_in[13];
    const float* b3  = (const float*)d_in[14];

    const int smem_bytes = SM_TOTAL * (int)sizeof(float);   // 81280
    cudaFuncSetAttribute(gcn_fused_kernel,
                         cudaFuncAttributeMaxDynamicSharedMemorySize, smem_bytes);
    gcn_fused_kernel<<<NBLOCKS, 256, smem_bytes>>>(
        x, W1, b1, g1, be1, m1, v1,
        W2, b2, g2, be2, m2, v2, W3, b3, (float*)d_out);
}

// round 4
// speedup vs baseline: 2.0181x; 1.2452x over previous
#include <cuda_runtime.h>
#include <cuda_bf16.h>
#include <math.h>

// ---------------------------------------------------------------------------
// Fused 3-layer GCN, fixed 21-node hand skeleton, 50000 graphs.
// R4: layer-2 GEMM on mma.sync.m16n8k16 bf16 (family-portable tensor path;
//     tcgen05/redux.f32 are 'a'-target-only and rejected by this toolchain).
//   tile = 4 graphs x 32 padded rows: M=128, N=128, K=64, bf16 hi/lo split
//   (AhBh + AhBl + AlBh), mix folded into A, BN scale folded into W2.
// ---------------------------------------------------------------------------

#define NODES   21
#define NCLS    29
#define GRID    625
#define TPB     20           // tiles per block: 625*20*4 graphs = 50000
#define R2C     0.70710678118654752440f

__device__ constexpr int   PAR[NODES] = {0,0,1,2,3, 0,5,6,7, 0,9,10,11, 0,13,14,15, 0,17,18,19};
__device__ constexpr float CP [NODES] = {0.f,R2C,.5f,.5f,.5f, R2C,.5f,.5f,.5f,
                                         R2C,.5f,.5f,.5f, R2C,.5f,.5f,.5f, R2C,.5f,.5f,.5f};

// ---- smem byte offsets ----------------------------------------------------
#define SB_AH   0            // A hi  [128 rows][144B]  (bf16, 64 k + pad)
#define SB_AL   18432        // A lo
#define SB_BH   36864        // B hi  [128 j ][144B]    (bf16, 64 k + pad)
#define SB_BL   55296        // B lo
#define SB_W3   73728        // W3/21 [128 j][32 c] f32
#define SB_T2   90112        // 128 f32
#define SB_B3   90624        // 32 f32
#define SB_PV   90752        // 8 strips x 128 f32 (partial pooled v)
#define SB_PY   94848        // 8 x 32 f32 (partial logits)
#define SB_TOT  95872

// ---- PTX helpers ----------------------------------------------------------
__device__ __forceinline__ unsigned smem_u32(const void* p) {
    unsigned a;
    asm("{ .reg .u64 t; cvta.to.shared.u64 t, %1; cvt.u32.u64 %0, t; }"
        : "=r"(a) : "l"(p));
    return a;
}
__device__ __forceinline__ void ldsm4(unsigned& r0, unsigned& r1,
                                      unsigned& r2, unsigned& r3, unsigned a) {
    asm volatile("ldmatrix.sync.aligned.m8n8.x4.shared.b16 {%0,%1,%2,%3}, [%4];"
                 : "=r"(r0), "=r"(r1), "=r"(r2), "=r"(r3) : "r"(a));
}
__device__ __forceinline__ void ldsm2(unsigned& r0, unsigned& r1, unsigned a) {
    asm volatile("ldmatrix.sync.aligned.m8n8.x2.shared.b16 {%0,%1}, [%2];"
                 : "=r"(r0), "=r"(r1) : "r"(a));
}
__device__ __forceinline__ void mma16816(float* c, unsigned a0, unsigned a1,
                                         unsigned a2, unsigned a3,
                                         unsigned b0, unsigned b1) {
    asm volatile(
        "mma.sync.aligned.m16n8k16.row.col.f32.bf16.bf16.f32 "
        "{%0,%1,%2,%3}, {%4,%5,%6,%7}, {%8,%9}, {%0,%1,%2,%3};"
        : "+f"(c[0]), "+f"(c[1]), "+f"(c[2]), "+f"(c[3])
        : "r"(a0), "r"(a1), "r"(a2), "r"(a3), "r"(b0), "r"(b1));
}
__device__ __forceinline__ float wnf(int n) {   // pooled column weight
    return (n == 0) ? 4.535533905932737f
         : (n > 20) ? 0.f
         : ((n & 3) == 0 ? 0.5f : 1.f);
}

// ---------------------------------------------------------------------------
__global__ void __launch_bounds__(256, 2)
gcn_mma_kernel(const float* __restrict__ x,
               const float* __restrict__ W1, const float* __restrict__ b1,
               const float* __restrict__ g1, const float* __restrict__ be1,
               const float* __restrict__ m1, const float* __restrict__ v1,
               const float* __restrict__ W2, const float* __restrict__ b2,
               const float* __restrict__ g2, const float* __restrict__ be2,
               const float* __restrict__ m2, const float* __restrict__ v2,
               const float* __restrict__ W3, const float* __restrict__ b3,
               float* __restrict__ out) {
    extern __shared__ char smc[];
    float* smf = (float*)smc;
    const unsigned sb = smem_u32(smc);
    const int tid  = threadIdx.x;
    const int lane = tid & 31;
    const int wid  = tid >> 5;          // 0..7

    // ---------------- staging (once per CTA) -------------------------------
    for (int i = tid; i < 36864 / 4; i += 256)       // zero both A planes
        ((unsigned*)(smc + SB_AH))[i] = 0u;
    for (int i = tid; i < 8192; i += 256) {          // B = W2 * diag(s2), hi/lo
        int k = i >> 7, j = i & 127;
        float s = g2[j] * rsqrtf(v2[j] + 1e-5f);
        float w = W2[i] * s;
        __nv_bfloat16 hi = __float2bfloat16(w);
        __nv_bfloat16 lo = __float2bfloat16(w - __bfloat162float(hi));
        *(__nv_bfloat16*)(smc + SB_BH + j * 144 + k * 2) = hi;
        *(__nv_bfloat16*)(smc + SB_BL + j * 144 + k * 2) = lo;
    }
    for (int i = tid; i < 4096; i += 256) {          // W3/21 padded [128][32]
        int j = i >> 5, c = i & 31;
        smf[SB_W3 / 4 + i] = (c < NCLS) ? W3[j * NCLS + c] * (1.f / 21.f) : 0.f;
    }
    if (tid < 128) {
        float s = g2[tid] * rsqrtf(v2[tid] + 1e-5f);
        smf[SB_T2 / 4 + tid] = (b2[tid] - m2[tid]) * s + be2[tid];
    }
    if (tid < NCLS) smf[SB_B3 / 4 + tid] = b3[tid];
    __syncthreads();

    // per-warp constants --------------------------------------------------
    // layer 1 (warps 0-3 only): graph q = wid, cols 2*lane, 2*lane+1
    float2 w1a, w1b, w1c, s1, t1;
    if (wid < 4) {
        int c2 = 2 * lane;
        w1a = make_float2(W1[c2],       W1[c2 + 1]);
        w1b = make_float2(W1[64 + c2],  W1[65 + c2]);
        w1c = make_float2(W1[128 + c2], W1[129 + c2]);
        float sa = g1[c2] * rsqrtf(v1[c2] + 1e-5f);
        float sbq = g1[c2 + 1] * rsqrtf(v1[c2 + 1] + 1e-5f);
        s1 = make_float2(sa, sbq);
        t1 = make_float2((b1[c2] - m1[c2]) * sa + be1[c2],
                         (b1[c2 + 1] - m1[c2 + 1]) * sbq + be1[c2 + 1]);
    }
    // mma strip s = wid: rows 16s..16s+15; node ids for epilogue rows
    const int strip_half = wid & 1;
    const float wn0 = wnf(strip_half * 16 + (lane >> 2));
    const float wn1 = wnf(strip_half * 16 + (lane >> 2) + 8);
    // ldmatrix base addresses (k-step added in loop)
    const unsigned aAddr0 = sb + SB_AH + (16 * wid + (lane & 15)) * 144
                          + (lane >> 4) * 16;
    const unsigned bAddr0 = sb + SB_BH + (lane & 7) * 144
                          + ((lane >> 3) & 1) * 16;

    for (int tt = 0; tt < TPB; ++tt) {
        const int gbase = (blockIdx.x * TPB + tt) * 4;

        // ---- phase 1: layer 1 + mix1 + BN + ReLU + mix2 -> A (warps 0-3) --
        if (wid < 4) {
            const float* xg = x + (size_t)(gbase + wid) * 63;
            float xv0 = xg[lane];
            float xv1 = (lane < 31) ? xg[32 + lane] : 0.f;
            float2 z[NODES], h[NODES];
            #pragma unroll
            for (int n = 0; n < NODES; ++n) {
                const int i0 = 3 * n, i1 = 3 * n + 1, i2 = 3 * n + 2;
                float xa = (i0 < 32) ? __shfl_sync(0xffffffffu, xv0, i0)
                                     : __shfl_sync(0xffffffffu, xv1, i0 - 32);
                float xb = (i1 < 32) ? __shfl_sync(0xffffffffu, xv0, i1)
                                     : __shfl_sync(0xffffffffu, xv1, i1 - 32);
                float xc = (i2 < 32) ? __shfl_sync(0xffffffffu, xv0, i2)
                                     : __shfl_sync(0xffffffffu, xv1, i2 - 32);
                z[n].x = fmaf(xa, w1a.x, fmaf(xb, w1b.x, xc * w1c.x));
                z[n].y = fmaf(xa, w1a.y, fmaf(xb, w1b.y, xc * w1c.y));
            }
            h[0].x = fmaxf(fmaf(z[0].x, s1.x, t1.x), 0.f);
            h[0].y = fmaxf(fmaf(z[0].y, s1.y, t1.y), 0.f);
            #pragma unroll
            for (int n = 1; n < NODES; ++n) {
                float mx_ = fmaf(0.5f, z[n].x, CP[n] * z[PAR[n]].x);
                float my_ = fmaf(0.5f, z[n].y, CP[n] * z[PAR[n]].y);
                h[n].x = fmaxf(fmaf(mx_, s1.x, t1.x), 0.f);
                h[n].y = fmaxf(fmaf(my_, s1.y, t1.y), 0.f);
            }
            #pragma unroll
            for (int n = 0; n < NODES; ++n) {
                float mx_, my_;
                if (n == 0) { mx_ = h[0].x; my_ = h[0].y; }
                else {
                    mx_ = fmaf(0.5f, h[n].x, CP[n] * h[PAR[n]].x);
                    my_ = fmaf(0.5f, h[n].y, CP[n] * h[PAR[n]].y);
                }
                __nv_bfloat16 hx = __float2bfloat16(mx_);
                __nv_bfloat16 hy = __float2bfloat16(my_);
                __nv_bfloat162 vh; vh.x = hx; vh.y = hy;
                __nv_bfloat162 vl;
                vl.x = __float2bfloat16(mx_ - __bfloat162float(hx));
                vl.y = __float2bfloat16(my_ - __bfloat162float(hy));
                unsigned off = (unsigned)(wid * 32 + n) * 144 + lane * 4;
                *(__nv_bfloat162*)(smc + SB_AH + off) = vh;
                *(__nv_bfloat162*)(smc + SB_AL + off) = vl;
            }
        }
        __syncthreads();                               // BAR1: A ready

        // ---- phase 2: 192 HMMA per warp (strip = wid) ---------------------
        float acc[16][4];
        #pragma unroll
        for (int n = 0; n < 16; ++n)
            #pragma unroll
            for (int c = 0; c < 4; ++c) acc[n][c] = 0.f;

        #pragma unroll
        for (int kk = 0; kk < 4; ++kk) {
            unsigned ah0, ah1, ah2, ah3, al0, al1, al2, al3;
            ldsm4(ah0, ah1, ah2, ah3, aAddr0 + kk * 32);
            ldsm4(al0, al1, al2, al3, aAddr0 + 18432 + kk * 32);
            #pragma unroll
            for (int n = 0; n < 16; ++n) {
                unsigned bh0, bh1, bl0, bl1;
                unsigned ba = bAddr0 + n * (8 * 144) + kk * 32;
                ldsm2(bh0, bh1, ba);
                ldsm2(bl0, bl1, ba + 18432);
                mma16816(acc[n], ah0, ah1, ah2, ah3, bh0, bh1);
                mma16816(acc[n], ah0, ah1, ah2, ah3, bl0, bl1);
                mma16816(acc[n], al0, al1, al2, al3, bh0, bh1);
            }
        }

        // ---- phase 3: epilogue pool (per strip) ---------------------------
        {
            float* PVs = smf + SB_PV / 4 + wid * 128;
            #pragma unroll
            for (int n = 0; n < 16; ++n) {
                int j0 = 8 * n + 2 * (lane & 3);
                float2 t2q = *(const float2*)(smf + SB_T2 / 4 + j0);
                float p0 = fmaf(wn0, fmaxf(acc[n][0] + t2q.x, 0.f),
                                wn1 * fmaxf(acc[n][2] + t2q.x, 0.f));
                float p1 = fmaf(wn0, fmaxf(acc[n][1] + t2q.y, 0.f),
                                wn1 * fmaxf(acc[n][3] + t2q.y, 0.f));
                #pragma unroll
                for (int o = 4; o < 32; o <<= 1) {
                    p0 += __shfl_xor_sync(0xffffffffu, p0, o);
                    p1 += __shfl_xor_sync(0xffffffffu, p1, o);
                }
                if (lane < 4) { PVs[j0] = p0; PVs[j0 + 1] = p1; }
            }
        }
        __syncthreads();                               // BAR2: PV ready

        // ---- phase 4: layer 3 partial (warp = graph x j-half) -------------
        {
            const int q = wid >> 1, hh = wid & 1;
            const float* PVa = smf + SB_PV / 4 + (2 * q) * 128;
            const float* PVb = PVa + 128;
            float y = 0.f;
            #pragma unroll 8
            for (int jj = 0; jj < 32; ++jj) {
                int j = 64 * hh + 2 * jj;
                float2 va = *(const float2*)(PVa + j);
                float2 vb = *(const float2*)(PVb + j);
                y = fmaf(va.x + vb.x, smf[SB_W3 / 4 + j * 32 + lane],
                    fmaf(va.y + vb.y, smf[SB_W3 / 4 + (j + 1) * 32 + lane], y));
            }
            smf[SB_PY / 4 + wid * 32 + lane] = y;
        }
        __syncthreads();                               // BAR3: PY ready

        // ---- phase 5: combine + log_softmax (warps 0-3) -------------------
        if (wid < 4) {
            float yy = smf[SB_PY / 4 + (2 * wid) * 32 + lane]
                     + smf[SB_PY / 4 + (2 * wid + 1) * 32 + lane];
            float logit = (lane < NCLS) ? yy + smf[SB_B3 / 4 + lane] : -1e30f;
            float mx = logit;
            #pragma unroll
            for (int o = 16; o; o >>= 1)
                mx = fmaxf(mx, __shfl_xor_sync(0xffffffffu, mx, o));
            float e = (lane < NCLS) ? expf(logit - mx) : 0.f;
            float s = e;
            #pragma unroll
            for (int o = 16; o; o >>= 1)
                s += __shfl_xor_sync(0xffffffffu, s, o);
            if (lane < NCLS)
                out[(size_t)(gbase + wid) * NCLS + lane] = logit - mx - logf(s);
        }
        // next tile's A writes are fenced by BAR1; PV/PY by BAR2/BAR3 chain
    }
}

extern "C" void kernel_launch(void* const* d_in, const int* in_sizes, int n_in,
                              void* d_out, int out_size) {
    const float* x   = (const float*)d_in[0];
    const float* W1  = (const float*)d_in[1];
    const float* b1  = (const float*)d_in[2];
    const float* g1  = (const float*)d_in[3];
    const float* be1 = (const float*)d_in[4];
    const float* m1  = (const float*)d_in[5];
    const float* v1  = (const float*)d_in[6];
    const float* W2  = (const float*)d_in[7];
    const float* b2  = (const float*)d_in[8];
    const float* g2  = (const float*)d_in[9];
    const float* be2 = (const float*)d_in[10];
    const float* m2  = (const float*)d_in[11];
    const float* v2  = (const float*)d_in[12];
    const float* W3  = (const float*)d_in[13];
    const float* b3  = (const float*)d_in[14];

    cudaFuncSetAttribute(gcn_mma_kernel,
                         cudaFuncAttributeMaxDynamicSharedMemorySize, SB_TOT);
    gcn_mma_kernel<<<GRID, 256, SB_TOT>>>(
        x, W1, b1, g1, be1, m1, v1,
        W2, b2, g2, be2, m2, v2, W3, b3, (float*)d_out);
}

// round 5
// speedup vs baseline: 5.4453x; 2.6983x over previous
#include <cuda_runtime.h>
#include <cuda_fp16.h>
#include <math.h>

// ---------------------------------------------------------------------------
// Fused 3-layer GCN, fixed 21-node hand skeleton, 50000 graphs.
// R5: transposed layer-2 GEMM on mma.sync m16n8k16 fp16:
//   C[j, node] = (W2'·s2)[j,k] @ h1mix[node,k],  tile = 8 graphs = 168 node
//   cols (NO padding).  W2 split fp16 hi/lo (2 products), h1 single fp16.
//   All 8 warps active in every phase; 3 barriers/tile; grid = 1 wave.
// ---------------------------------------------------------------------------

#define NODES   21
#define NCLS    29
#define NTILES  6250          // 50000 / 8
#define GRID    296           // 148 SM x 2 CTA
#define R2C     0.70710678118654752440f
#define WROOT   4.535533905932737f

__device__ constexpr int   PAR[NODES] = {0,0,1,2,3, 0,5,6,7, 0,9,10,11, 0,13,14,15, 0,17,18,19};
__device__ constexpr float CP [NODES] = {0.f,R2C,.5f,.5f,.5f, R2C,.5f,.5f,.5f,
                                         R2C,.5f,.5f,.5f, R2C,.5f,.5f,.5f, R2C,.5f,.5f,.5f};

// ---- smem byte offsets ----------------------------------------------------
#define SB_H    0             // h1mix fp16 [168 rows][144B]          24192
#define SB_AH   24192         // W2' hi fp16 [128 j][144B]            18432
#define SB_AL   42624         // W2' lo                               18432
#define SB_W3   61056         // W3/21 [128 j][32 c] f32              16384
#define SB_PV   77440         // pooled v [128 j][8 g] f32            4096
#define SB_PY   81536         // partial y [8 w][8 g][32 c] f32       8192
#define SB_T2   89728         // 128 f32
#define SB_B3   90240         // 32 f32
#define SB_TOT  90368

// ---- PTX helpers ----------------------------------------------------------
__device__ __forceinline__ unsigned smem_u32(const void* p) {
    unsigned a;
    asm("{ .reg .u64 t; cvta.to.shared.u64 t, %1; cvt.u32.u64 %0, t; }"
        : "=r"(a) : "l"(p));
    return a;
}
__device__ __forceinline__ void ldsm4(unsigned& r0, unsigned& r1,
                                      unsigned& r2, unsigned& r3, unsigned a) {
    asm volatile("ldmatrix.sync.aligned.m8n8.x4.shared.b16 {%0,%1,%2,%3}, [%4];"
                 : "=r"(r0), "=r"(r1), "=r"(r2), "=r"(r3) : "r"(a));
}
__device__ __forceinline__ void ldsm2(unsigned& r0, unsigned& r1, unsigned a) {
    asm volatile("ldmatrix.sync.aligned.m8n8.x2.shared.b16 {%0,%1}, [%2];"
                 : "=r"(r0), "=r"(r1) : "r"(a));
}
__device__ __forceinline__ void mma16816(float* c, unsigned a0, unsigned a1,
                                         unsigned a2, unsigned a3,
                                         unsigned b0, unsigned b1) {
    asm volatile(
        "mma.sync.aligned.m16n8k16.row.col.f32.f16.f16.f32 "
        "{%0,%1,%2,%3}, {%4,%5,%6,%7}, {%8,%9}, {%0,%1,%2,%3};"
        : "+f"(c[0]), "+f"(c[1]), "+f"(c[2]), "+f"(c[3])
        : "r"(a0), "r"(a1), "r"(a2), "r"(a3), "r"(b0), "r"(b1));
}
__device__ __forceinline__ float wsel(int ln) {     // pooled column weight
    return (ln == 0) ? WROOT : ((ln & 3) == 0 ? 0.5f : 1.0f);
}
__device__ __forceinline__ float pick4(const float* v, int s) {
    return (s == 0) ? v[0] : (s == 1) ? v[1] : (s == 2) ? v[2] : v[3];
}

// ---------------------------------------------------------------------------
__global__ void __launch_bounds__(256, 2)
gcn_t_kernel(const float* __restrict__ x,
             const float* __restrict__ W1, const float* __restrict__ b1,
             const float* __restrict__ g1, const float* __restrict__ be1,
             const float* __restrict__ m1, const float* __restrict__ v1,
             const float* __restrict__ W2, const float* __restrict__ b2,
             const float* __restrict__ g2, const float* __restrict__ be2,
             const float* __restrict__ m2, const float* __restrict__ v2,
             const float* __restrict__ W3, const float* __restrict__ b3,
             float* __restrict__ out) {
    extern __shared__ char smc[];
    float* smf = (float*)smc;
    const unsigned sb = smem_u32(smc);
    const int tid  = threadIdx.x;
    const int lane = tid & 31;
    const int wid  = tid >> 5;          // 0..7

    // ---------------- staging (once per CTA) -------------------------------
    // A = (W2^T * diag(s2)) fp16 hi/lo, [j][144B] rows
    for (int i = tid; i < 8192; i += 256) {
        int j = i & 127, k = i >> 7;
        float s = g2[j] * rsqrtf(v2[j] + 1e-5f);
        float w = W2[k * 128 + j] * s;
        __half hi = __float2half(w);
        __half lo = __float2half(w - __half2float(hi));
        *(__half*)(smc + SB_AH + j * 144 + k * 2) = hi;
        *(__half*)(smc + SB_AL + j * 144 + k * 2) = lo;
    }
    for (int i = tid; i < 4096; i += 256) {          // W3/21 padded [128][32]
        int j = i >> 5, c = i & 31;
        smf[SB_W3 / 4 + i] = (c < NCLS) ? W3[j * NCLS + c] * (1.f / 21.f) : 0.f;
    }
    if (tid < 128) {
        float s = g2[tid] * rsqrtf(v2[tid] + 1e-5f);
        smf[SB_T2 / 4 + tid] = (b2[tid] - m2[tid]) * s + be2[tid];
    }
    if (tid < NCLS) smf[SB_B3 / 4 + tid] = b3[tid];
    __syncthreads();

    // per-lane layer-1 constants (cols 2*lane, 2*lane+1)
    float2 w1a, w1b, w1c, s1, t1;
    {
        int c2 = 2 * lane;
        w1a = make_float2(W1[c2],       W1[c2 + 1]);
        w1b = make_float2(W1[64 + c2],  W1[65 + c2]);
        w1c = make_float2(W1[128 + c2], W1[129 + c2]);
        float sa = g1[c2] * rsqrtf(v1[c2] + 1e-5f);
        float sbq = g1[c2 + 1] * rsqrtf(v1[c2 + 1] + 1e-5f);
        s1 = make_float2(sa, sbq);
        t1 = make_float2((b1[c2] - m1[c2]) * sa + be1[c2],
                         (b1[c2 + 1] - m1[c2 + 1]) * sbq + be1[c2 + 1]);
    }
    const float t2r0 = smf[SB_T2 / 4 + 16 * wid + (lane >> 2)];
    const float t2r1 = smf[SB_T2 / 4 + 16 * wid + (lane >> 2) + 8];
    const unsigned aAddrH = sb + SB_AH + (16 * wid + (lane & 15)) * 144
                          + (lane >> 4) * 16;
    const unsigned aAddrL = aAddrH + (SB_AL - SB_AH);
    const unsigned bAddr  = sb + SB_H + (lane & 7) * 144
                          + ((lane >> 3) & 1) * 16;
    const int cp2 = 2 * (lane & 3);

    for (int tile = blockIdx.x; tile < NTILES; tile += GRID) {
        const int gbase = tile * 8;

        // ---- phase 1: layer 1 + mix + BN + ReLU + mix2 -> H (warp=graph) --
        {
            const float* xg = x + (size_t)(gbase + wid) * 63;
            float xv0 = xg[lane];
            float xv1 = (lane < 31) ? xg[32 + lane] : 0.f;
            float2 z[NODES], h[NODES];
            #pragma unroll
            for (int n = 0; n < NODES; ++n) {
                const int i0 = 3 * n, i1 = 3 * n + 1, i2 = 3 * n + 2;
                float xa = (i0 < 32) ? __shfl_sync(0xffffffffu, xv0, i0)
                                     : __shfl_sync(0xffffffffu, xv1, i0 - 32);
                float xb = (i1 < 32) ? __shfl_sync(0xffffffffu, xv0, i1)
                                     : __shfl_sync(0xffffffffu, xv1, i1 - 32);
                float xc = (i2 < 32) ? __shfl_sync(0xffffffffu, xv0, i2)
                                     : __shfl_sync(0xffffffffu, xv1, i2 - 32);
                z[n].x = fmaf(xa, w1a.x, fmaf(xb, w1b.x, xc * w1c.x));
                z[n].y = fmaf(xa, w1a.y, fmaf(xb, w1b.y, xc * w1c.y));
            }
            h[0].x = fmaxf(fmaf(z[0].x, s1.x, t1.x), 0.f);
            h[0].y = fmaxf(fmaf(z[0].y, s1.y, t1.y), 0.f);
            #pragma unroll
            for (int n = 1; n < NODES; ++n) {
                float mx_ = fmaf(0.5f, z[n].x, CP[n] * z[PAR[n]].x);
                float my_ = fmaf(0.5f, z[n].y, CP[n] * z[PAR[n]].y);
                h[n].x = fmaxf(fmaf(mx_, s1.x, t1.x), 0.f);
                h[n].y = fmaxf(fmaf(my_, s1.y, t1.y), 0.f);
            }
            #pragma unroll
            for (int n = 0; n < NODES; ++n) {
                float mx_, my_;
                if (n == 0) { mx_ = h[0].x; my_ = h[0].y; }
                else {
                    mx_ = fmaf(0.5f, h[n].x, CP[n] * h[PAR[n]].x);
                    my_ = fmaf(0.5f, h[n].y, CP[n] * h[PAR[n]].y);
                }
                *(__half2*)(smc + SB_H + (21 * wid + n) * 144 + lane * 4) =
                    __floats2half2_rn(mx_, my_);
            }
        }
        __syncthreads();                              // BAR1: H ready

        // ---- phase 2: MMA  C[j-strip, 168 nodes] --------------------------
        float acc[21][4];
        #pragma unroll
        for (int nt = 0; nt < 21; ++nt)
            #pragma unroll
            for (int c = 0; c < 4; ++c) acc[nt][c] = 0.f;

        #pragma unroll
        for (int kk = 0; kk < 4; ++kk) {
            unsigned ah0, ah1, ah2, ah3, al0, al1, al2, al3;
            ldsm4(ah0, ah1, ah2, ah3, aAddrH + kk * 32);
            ldsm4(al0, al1, al2, al3, aAddrL + kk * 32);
            #pragma unroll
            for (int nt = 0; nt < 21; ++nt) {
                unsigned b0, b1;
                ldsm2(b0, b1, bAddr + nt * (8 * 144) + kk * 32);
                mma16816(acc[nt], ah0, ah1, ah2, ah3, b0, b1);
                mma16816(acc[nt], al0, al1, al2, al3, b0, b1);
            }
        }

        // ---- phase 3: epilogue pool (per graph, static indices) -----------
        float vA[8], vB[8];
        #pragma unroll
        for (int g = 0; g < 8; ++g) { vA[g] = 0.f; vB[g] = 0.f; }
        #pragma unroll
        for (int nt = 0; nt < 21; ++nt) {
            const int gl = (8 * nt) / 21, gh = (8 * nt + 7) / 21;
            const int bnd = 21 * (gl + 1);
            const int n0 = 8 * nt + cp2, n1 = n0 + 1;
            const int l0 = n0 - ((n0 < bnd) ? 21 * gl : bnd);
            const int l1 = n1 - ((n1 < bnd) ? 21 * gl : bnd);
            float q0 = fmaxf(acc[nt][0] + t2r0, 0.f) * wsel(l0);
            float q1 = fmaxf(acc[nt][1] + t2r0, 0.f) * wsel(l1);
            float q2 = fmaxf(acc[nt][2] + t2r1, 0.f) * wsel(l0);
            float q3 = fmaxf(acc[nt][3] + t2r1, 0.f) * wsel(l1);
            if (gl == gh) {
                vA[gl] += q0 + q1;
                vB[gl] += q2 + q3;
            } else {
                float aLo = ((n0 < bnd) ? q0 : 0.f) + ((n1 < bnd) ? q1 : 0.f);
                float bLo = ((n0 < bnd) ? q2 : 0.f) + ((n1 < bnd) ? q3 : 0.f);
                vA[gl] += aLo;          vB[gl] += bLo;
                vA[gh] += (q0 + q1) - aLo;
                vB[gh] += (q2 + q3) - bLo;
            }
        }
        #pragma unroll
        for (int g = 0; g < 8; ++g) {                 // sum the 4 col-slices
            vA[g] += __shfl_xor_sync(0xffffffffu, vA[g], 1);
            vA[g] += __shfl_xor_sync(0xffffffffu, vA[g], 2);
            vB[g] += __shfl_xor_sync(0xffffffffu, vB[g], 1);
            vB[g] += __shfl_xor_sync(0xffffffffu, vB[g], 2);
        }
        {
            const int gs = lane & 3;
            const int j0 = 16 * wid + (lane >> 2);
            smf[SB_PV / 4 + j0 * 8 + gs]           = pick4(vA, gs);
            smf[SB_PV / 4 + j0 * 8 + gs + 4]       = pick4(vA + 4, gs);
            smf[SB_PV / 4 + (j0 + 8) * 8 + gs]     = pick4(vB, gs);
            smf[SB_PV / 4 + (j0 + 8) * 8 + gs + 4] = pick4(vB + 4, gs);
        }
        __syncthreads();                              // BAR2: PV ready

        // ---- phase 4: layer 3 partial over j-strip ------------------------
        {
            float y[8];
            #pragma unroll
            for (int g = 0; g < 8; ++g) y[g] = 0.f;
            #pragma unroll
            for (int jj = 0; jj < 16; ++jj) {
                const int j = 16 * wid + jj;
                float wc = smf[SB_W3 / 4 + j * 32 + lane];
                float4 p0 = *(const float4*)(smf + SB_PV / 4 + j * 8);
                float4 p1 = *(const float4*)(smf + SB_PV / 4 + j * 8 + 4);
                y[0] = fmaf(p0.x, wc, y[0]); y[1] = fmaf(p0.y, wc, y[1]);
                y[2] = fmaf(p0.z, wc, y[2]); y[3] = fmaf(p0.w, wc, y[3]);
                y[4] = fmaf(p1.x, wc, y[4]); y[5] = fmaf(p1.y, wc, y[5]);
                y[6] = fmaf(p1.z, wc, y[6]); y[7] = fmaf(p1.w, wc, y[7]);
            }
            #pragma unroll
            for (int g = 0; g < 8; ++g)
                smf[SB_PY / 4 + wid * 256 + g * 32 + lane] = y[g];
        }
        __syncthreads();                              // BAR3: PY ready

        // ---- phase 5: combine + log_softmax (warp = graph) ----------------
        {
            float yy = 0.f;
            #pragma unroll
            for (int w = 0; w < 8; ++w)
                yy += smf[SB_PY / 4 + w * 256 + wid * 32 + lane];
            float logit = (lane < NCLS) ? yy + smf[SB_B3 / 4 + lane] : -1e30f;
            float mx = logit;
            #pragma unroll
            for (int o = 16; o; o >>= 1)
                mx = fmaxf(mx, __shfl_xor_sync(0xffffffffu, mx, o));
            float e = (lane < NCLS) ? expf(logit - mx) : 0.f;
            float s = e;
            #pragma unroll
            for (int o = 16; o; o >>= 1)
                s += __shfl_xor_sync(0xffffffffu, s, o);
            if (lane < NCLS)
                out[(size_t)(gbase + wid) * NCLS + lane] = logit - mx - logf(s);
        }
        // next tile's H writes guarded by BAR1; PV/PY by BAR2/BAR3 chain
    }
}

extern "C" void kernel_launch(void* const* d_in, const int* in_sizes, int n_in,
                              void* d_out, int out_size) {
    const float* x   = (const float*)d_in[0];
    const float* W1  = (const float*)d_in[1];
    const float* b1  = (const float*)d_in[2];
    const float* g1  = (const float*)d_in[3];
    const float* be1 = (const float*)d_in[4];
    const float* m1  = (const float*)d_in[5];
    const float* v1  = (const float*)d_in[6];
    const float* W2  = (const float*)d_in[7];
    const float* b2  = (const float*)d_in[8];
    const float* g2  = (const float*)d_in[9];
    const float* be2 = (const float*)d_in[10];
    const float* m2  = (const float*)d_in[11];
    const float* v2  = (const float*)d_in[12];
    const float* W3  = (const float*)d_in[13];
    const float* b3  = (const float*)d_in[14];

    cudaFuncSetAttribute(gcn_t_kernel,
                         cudaFuncAttributeMaxDynamicSharedMemorySize, SB_TOT);
    gcn_t_kernel<<<GRID, 256, SB_TOT>>>(
        x, W1, b1, g1, be1, m1, v1,
        W2, b2, g2, be2, m2, v2, W3, b3, (float*)d_out);
}

// round 6
// speedup vs baseline: 6.6617x; 1.2234x over previous
#include <cuda_runtime.h>
#include <cuda_fp16.h>
#include <math.h>

// ---------------------------------------------------------------------------
// Fused 3-layer GCN, fixed 21-node hand skeleton, 50000 graphs.
// R6: single fp16 product (R5 evidence: fp16-operand error ~2e-6 << 1e-3),
//     register diet (per-finger layer-1, fused MMA epilogue) -> 80 regs,
//     smem 73.2KB -> 3 CTAs/SM (24 warps), persistent grid 444.
//   C[j, node] = (W2'·s2)[j,k] @ h1mix[node,k], tile = 8 graphs = 168 cols.
// ---------------------------------------------------------------------------

#define NODES   21
#define NCLS    29
#define NTILES  6250          // 50000 / 8
#define GRID    444           // 148 SM x 3 CTA
#define R2C     0.70710678118654752440f
#define WROOT   4.535533905932737f

// ---- smem byte offsets ----------------------------------------------------
#define SB_H    0             // h1mix fp16 [168 rows][144B]          24192
#define SB_AH   24192         // W2'*s2 fp16 [128 j][144B]            18432
#define SB_W3   42624         // W3/21 [128 j][32 c] f32              16384
#define SB_PV   59008         // pooled v [128 j][8 g] f32            4096
#define SB_PY   63104         // partial y [8 w][8 g][32 c] f32       8192
#define SB_T2   71296         // 128 f32
#define SB_B3   71808         // 32 f32
#define SB_C    71936         // W1 [3][64] f32                       768
#define SB_S1   72704         // 64 f32
#define SB_T1   72960         // 64 f32
#define SB_TOT  73216         // x3 = 219,648 <= 228KB carveout

// ---- PTX helpers ----------------------------------------------------------
__device__ __forceinline__ unsigned smem_u32(const void* p) {
    unsigned a;
    asm("{ .reg .u64 t; cvta.to.shared.u64 t, %1; cvt.u32.u64 %0, t; }"
        : "=r"(a) : "l"(p));
    return a;
}
__device__ __forceinline__ void ldsm4(unsigned& r0, unsigned& r1,
                                      unsigned& r2, unsigned& r3, unsigned a) {
    asm volatile("ldmatrix.sync.aligned.m8n8.x4.shared.b16 {%0,%1,%2,%3}, [%4];"
                 : "=r"(r0), "=r"(r1), "=r"(r2), "=r"(r3) : "r"(a));
}
__device__ __forceinline__ void ldsm2(unsigned& r0, unsigned& r1, unsigned a) {
    asm volatile("ldmatrix.sync.aligned.m8n8.x2.shared.b16 {%0,%1}, [%2];"
                 : "=r"(r0), "=r"(r1) : "r"(a));
}
__device__ __forceinline__ void mma16816(float* c, unsigned a0, unsigned a1,
                                         unsigned a2, unsigned a3,
                                         unsigned b0, unsigned b1) {
    asm volatile(
        "mma.sync.aligned.m16n8k16.row.col.f32.f16.f16.f32 "
        "{%0,%1,%2,%3}, {%4,%5,%6,%7}, {%8,%9}, {%0,%1,%2,%3};"
        : "+f"(c[0]), "+f"(c[1]), "+f"(c[2]), "+f"(c[3])
        : "r"(a0), "r"(a1), "r"(a2), "r"(a3), "r"(b0), "r"(b1));
}
__device__ __forceinline__ float wsel(int ln) {     // pooled node weight
    return (ln == 0) ? WROOT : ((ln & 3) == 0 ? 0.5f : 1.0f);
}
__device__ __forceinline__ float pick4(const float* v, int s) {
    return (s == 0) ? v[0] : (s == 1) ? v[1] : (s == 2) ? v[2] : v[3];
}

// ---------------------------------------------------------------------------
__global__ void __launch_bounds__(256, 3)
gcn_t3_kernel(const float* __restrict__ x,
              const float* __restrict__ W1, const float* __restrict__ b1,
              const float* __restrict__ g1, const float* __restrict__ be1,
              const float* __restrict__ m1, const float* __restrict__ v1,
              const float* __restrict__ W2, const float* __restrict__ b2,
              const float* __restrict__ g2, const float* __restrict__ be2,
              const float* __restrict__ m2, const float* __restrict__ v2,
              const float* __restrict__ W3, const float* __restrict__ b3,
              float* __restrict__ out) {
    extern __shared__ char smc[];
    float* smf = (float*)smc;
    const unsigned sb = smem_u32(smc);
    const int tid  = threadIdx.x;
    const int lane = tid & 31;
    const int wid  = tid >> 5;          // 0..7

    // ---------------- staging (once per CTA) -------------------------------
    for (int i = tid; i < 8192; i += 256) {          // A = W2^T * diag(s2)
        int j = i & 127, k = i >> 7;
        float s = g2[j] * rsqrtf(v2[j] + 1e-5f);
        *(__half*)(smc + SB_AH + j * 144 + k * 2) =
            __float2half(W2[k * 128 + j] * s);
    }
    for (int i = tid; i < 4096; i += 256) {          // W3/21 padded [128][32]
        int j = i >> 5, c = i & 31;
        smf[SB_W3 / 4 + i] = (c < NCLS) ? W3[j * NCLS + c] * (1.f / 21.f) : 0.f;
    }
    if (tid < 128) {
        float s = g2[tid] * rsqrtf(v2[tid] + 1e-5f);
        smf[SB_T2 / 4 + tid] = (b2[tid] - m2[tid]) * s + be2[tid];
    }
    if (tid < NCLS) smf[SB_B3 / 4 + tid] = b3[tid];
    for (int i = tid; i < 192; i += 256) smf[SB_C / 4 + i] = W1[i];
    if (tid < 64) {
        float s = g1[tid] * rsqrtf(v1[tid] + 1e-5f);
        smf[SB_S1 / 4 + tid] = s;
        smf[SB_T1 / 4 + tid] = (b1[tid] - m1[tid]) * s + be1[tid];
    }
    __syncthreads();

    const float t2r0 = smf[SB_T2 / 4 + 16 * wid + (lane >> 2)];
    const float t2r1 = smf[SB_T2 / 4 + 16 * wid + (lane >> 2) + 8];
    const unsigned aAddr = sb + SB_AH + (16 * wid + (lane & 15)) * 144
                         + (lane >> 4) * 16;
    const unsigned bAddr = sb + SB_H + (lane & 7) * 144
                         + ((lane >> 3) & 1) * 16;
    const int cp2 = 2 * (lane & 3);

    for (int tile = blockIdx.x; tile < NTILES; tile += GRID) {
        const int gbase = tile * 8;

        // ---- phase 1: layer 1 + mix + BN + ReLU + mix2 -> H (warp=graph) --
        {
            const float2 w1a = ((const float2*)(smf + SB_C / 4))[lane];
            const float2 w1b = ((const float2*)(smf + SB_C / 4 + 64))[lane];
            const float2 w1c = ((const float2*)(smf + SB_C / 4 + 128))[lane];
            const float2 s1  = ((const float2*)(smf + SB_S1 / 4))[lane];
            const float2 t1  = ((const float2*)(smf + SB_T1 / 4))[lane];
            const float* xg = x + (size_t)(gbase + wid) * 63;
            const float xv0 = xg[lane];
            const float xv1 = (lane < 31) ? xg[32 + lane] : 0.f;

            // node 0
            float2 z0, h0;
            {
                float xa = __shfl_sync(0xffffffffu, xv0, 0);
                float xb = __shfl_sync(0xffffffffu, xv0, 1);
                float xc = __shfl_sync(0xffffffffu, xv0, 2);
                z0.x = fmaf(xa, w1a.x, fmaf(xb, w1b.x, xc * w1c.x));
                z0.y = fmaf(xa, w1a.y, fmaf(xb, w1b.y, xc * w1c.y));
                h0.x = fmaxf(fmaf(z0.x, s1.x, t1.x), 0.f);
                h0.y = fmaxf(fmaf(z0.y, s1.y, t1.y), 0.f);
                *(__half2*)(smc + SB_H + (21 * wid) * 144 + lane * 4) =
                    __floats2half2_rn(h0.x, h0.y);
            }
            // five independent finger chains of 4 nodes
            #pragma unroll
            for (int f = 0; f < 5; ++f) {
                float2 zp = z0, hp = h0;
                #pragma unroll
                for (int i = 0; i < 4; ++i) {
                    const int n = 1 + 4 * f + i;
                    const float cp = (i == 0) ? R2C : 0.5f;
                    const int i0 = 3 * n;
                    float xa = (i0 < 32) ? __shfl_sync(0xffffffffu, xv0, i0)
                                         : __shfl_sync(0xffffffffu, xv1, i0 - 32);
                    float xb = (i0 + 1 < 32) ? __shfl_sync(0xffffffffu, xv0, i0 + 1)
                                             : __shfl_sync(0xffffffffu, xv1, i0 - 31);
                    float xc = (i0 + 2 < 32) ? __shfl_sync(0xffffffffu, xv0, i0 + 2)
                                             : __shfl_sync(0xffffffffu, xv1, i0 - 30);
                    float2 zn, hn;
                    zn.x = fmaf(xa, w1a.x, fmaf(xb, w1b.x, xc * w1c.x));
                    zn.y = fmaf(xa, w1a.y, fmaf(xb, w1b.y, xc * w1c.y));
                    float m1x = fmaf(0.5f, zn.x, cp * zp.x);
                    float m1y = fmaf(0.5f, zn.y, cp * zp.y);
                    hn.x = fmaxf(fmaf(m1x, s1.x, t1.x), 0.f);
                    hn.y = fmaxf(fmaf(m1y, s1.y, t1.y), 0.f);
                    float m2x = fmaf(0.5f, hn.x, cp * hp.x);
                    float m2y = fmaf(0.5f, hn.y, cp * hp.y);
                    *(__half2*)(smc + SB_H + (21 * wid + n) * 144 + lane * 4) =
                        __floats2half2_rn(m2x, m2y);
                    zp = zn; hp = hn;
                }
            }
        }
        __syncthreads();                              // BAR1: H ready

        // ---- phase 2+3: MMA with fused pooling epilogue -------------------
        {
            unsigned ah[4][4];
            #pragma unroll
            for (int kk = 0; kk < 4; ++kk)
                ldsm4(ah[kk][0], ah[kk][1], ah[kk][2], ah[kk][3],
                      aAddr + kk * 32);

            float vA[8], vB[8];
            #pragma unroll
            for (int g = 0; g < 8; ++g) { vA[g] = 0.f; vB[g] = 0.f; }

            #pragma unroll
            for (int nt = 0; nt < 21; ++nt) {
                float acc[4] = {0.f, 0.f, 0.f, 0.f};
                #pragma unroll
                for (int kk = 0; kk < 4; ++kk) {
                    unsigned b0, b1;
                    ldsm2(b0, b1, bAddr + nt * (8 * 144) + kk * 32);
                    mma16816(acc, ah[kk][0], ah[kk][1], ah[kk][2], ah[kk][3],
                             b0, b1);
                }
                // pooling epilogue for these 8 node-columns
                const int gl = (8 * nt) / 21, gh = (8 * nt + 7) / 21;
                const int bnd = 21 * (gl + 1);
                const int n0 = 8 * nt + cp2, n1 = n0 + 1;
                const int l0 = n0 - ((n0 < bnd) ? 21 * gl : bnd);
                const int l1 = n1 - ((n1 < bnd) ? 21 * gl : bnd);
                float q0 = fmaxf(acc[0] + t2r0, 0.f) * wsel(l0);
                float q1 = fmaxf(acc[1] + t2r0, 0.f) * wsel(l1);
                float q2 = fmaxf(acc[2] + t2r1, 0.f) * wsel(l0);
                float q3 = fmaxf(acc[3] + t2r1, 0.f) * wsel(l1);
                if (gl == gh) {
                    vA[gl] += q0 + q1;
                    vB[gl] += q2 + q3;
                } else {
                    float aLo = ((n0 < bnd) ? q0 : 0.f) + ((n1 < bnd) ? q1 : 0.f);
                    float bLo = ((n0 < bnd) ? q2 : 0.f) + ((n1 < bnd) ? q3 : 0.f);
                    vA[gl] += aLo;          vB[gl] += bLo;
                    vA[gh] += (q0 + q1) - aLo;
                    vB[gh] += (q2 + q3) - bLo;
                }
            }
            #pragma unroll
            for (int g = 0; g < 8; ++g) {             // sum 4 col-slices
                vA[g] += __shfl_xor_sync(0xffffffffu, vA[g], 1);
                vA[g] += __shfl_xor_sync(0xffffffffu, vA[g], 2);
                vB[g] += __shfl_xor_sync(0xffffffffu, vB[g], 1);
                vB[g] += __shfl_xor_sync(0xffffffffu, vB[g], 2);
            }
            const int gs = lane & 3;
            const int j0 = 16 * wid + (lane >> 2);
            smf[SB_PV / 4 + j0 * 8 + gs]           = pick4(vA, gs);
            smf[SB_PV / 4 + j0 * 8 + gs + 4]       = pick4(vA + 4, gs);
            smf[SB_PV / 4 + (j0 + 8) * 8 + gs]     = pick4(vB, gs);
            smf[SB_PV / 4 + (j0 + 8) * 8 + gs + 4] = pick4(vB + 4, gs);
        }
        __syncthreads();                              // BAR2: PV ready

        // ---- phase 4: layer 3 partial over j-strip ------------------------
        {
            float y[8];
            #pragma unroll
            for (int g = 0; g < 8; ++g) y[g] = 0.f;
            #pragma unroll
            for (int jj = 0; jj < 16; ++jj) {
                const int j = 16 * wid + jj;
                float wc = smf[SB_W3 / 4 + j * 32 + lane];
                float4 p0 = *(const float4*)(smf + SB_PV / 4 + j * 8);
                float4 p1 = *(const float4*)(smf + SB_PV / 4 + j * 8 + 4);
                y[0] = fmaf(p0.x, wc, y[0]); y[1] = fmaf(p0.y, wc, y[1]);
                y[2] = fmaf(p0.z, wc, y[2]); y[3] = fmaf(p0.w, wc, y[3]);
                y[4] = fmaf(p1.x, wc, y[4]); y[5] = fmaf(p1.y, wc, y[5]);
                y[6] = fmaf(p1.z, wc, y[6]); y[7] = fmaf(p1.w, wc, y[7]);
            }
            #pragma unroll
            for (int g = 0; g < 8; ++g)
                smf[SB_PY / 4 + wid * 256 + g * 32 + lane] = y[g];
        }
        __syncthreads();                              // BAR3: PY ready

        // ---- phase 5: combine + log_softmax (warp = graph) ----------------
        {
            float yy = 0.f;
            #pragma unroll
            for (int w = 0; w < 8; ++w)
                yy += smf[SB_PY / 4 + w * 256 + wid * 32 + lane];
            float logit = (lane < NCLS) ? yy + smf[SB_B3 / 4 + lane] : -1e30f;
            float mx = logit;
            #pragma unroll
            for (int o = 16; o; o >>= 1)
                mx = fmaxf(mx, __shfl_xor_sync(0xffffffffu, mx, o));
            float e = (lane < NCLS) ? expf(logit - mx) : 0.f;
            float s = e;
            #pragma unroll
            for (int o = 16; o; o >>= 1)
                s += __shfl_xor_sync(0xffffffffu, s, o);
            if (lane < NCLS)
                out[(size_t)(gbase + wid) * NCLS + lane] = logit - mx - logf(s);
        }
        // next tile's H writes guarded by BAR1; PV/PY by BAR2/BAR3 chain
    }
}

extern "C" void kernel_launch(void* const* d_in, const int* in_sizes, int n_in,
                              void* d_out, int out_size) {
    const float* x   = (const float*)d_in[0];
    const float* W1  = (const float*)d_in[1];
    const float* b1  = (const float*)d_in[2];
    const float* g1  = (const float*)d_in[3];
    const float* be1 = (const float*)d_in[4];
    const float* m1  = (const float*)d_in[5];
    const float* v1  = (const float*)d_in[6];
    const float* W2  = (const float*)d_in[7];
    const float* b2  = (const float*)d_in[8];
    const float* g2  = (const float*)d_in[9];
    const float* be2 = (const float*)d_in[10];
    const float* m2  = (const float*)d_in[11];
    const float* v2  = (const float*)d_in[12];
    const float* W3  = (const float*)d_in[13];
    const float* b3  = (const float*)d_in[14];

    cudaFuncSetAttribute(gcn_t3_kernel,
                         cudaFuncAttributeMaxDynamicSharedMemorySize, SB_TOT);
    gcn_t3_kernel<<<GRID, 256, SB_TOT>>>(
        x, W1, b1, g1, be1, m1, v1,
        W2, b2, g2, be2, m2, v2, W3, b3, (float*)d_out);
}

// round 7
// speedup vs baseline: 6.9160x; 1.0382x over previous
#include <cuda_runtime.h>
#include <cuda_fp16.h>
#include <math.h>

// ---------------------------------------------------------------------------
// Fused 3-layer GCN, fixed 21-node hand skeleton, 50000 graphs.
// R7: B-traffic halving. Warp = (j-strip of 32) x (node half of ~84 cols):
//   M=32 per warp -> 11 nt-tiles (nt 10 shared, masked), B wf 168->88/warp.
//   A fragments (static W2 strip) ldsm'd ONCE per kernel: 0 per-tile A wf.
//   Single fp16 product, 3 CTAs/SM, persistent grid.
// ---------------------------------------------------------------------------

#define NODES   21
#define NCLS    29
#define NTILES  6250          // 50000 / 8
#define GRID    444           // 148 SM x 3 CTA
#define R2C     0.70710678118654752440f
#define WROOT   4.535533905932737f

// ---- smem byte offsets ----------------------------------------------------
#define SB_H    0             // h1mix fp16 [168 rows][144B]          24192
#define SB_AH   24192         // W2'*s2 fp16 [128 j][144B]            18432
#define SB_W3   42624         // W3/21 [128 j][32 c] f32              16384
#define SB_PV   59008         // pooled v [128 j][8 g] f32            4096
#define SB_PY   63104         // partial y [8 w][8 g][32 c] f32       8192
#define SB_T2   71296         // 128 f32
#define SB_B3   71808         // 32 f32
#define SB_C    71936         // W1 [3][64] f32                       768
#define SB_S1   72704         // 64 f32
#define SB_T1   72960         // 64 f32
#define SB_TOT  73216         // x3 = 219,648 <= 228KB carveout

// ---- PTX helpers ----------------------------------------------------------
__device__ __forceinline__ unsigned smem_u32(const void* p) {
    unsigned a;
    asm("{ .reg .u64 t; cvta.to.shared.u64 t, %1; cvt.u32.u64 %0, t; }"
        : "=r"(a) : "l"(p));
    return a;
}
__device__ __forceinline__ void ldsm4(unsigned& r0, unsigned& r1,
                                      unsigned& r2, unsigned& r3, unsigned a) {
    asm volatile("ldmatrix.sync.aligned.m8n8.x4.shared.b16 {%0,%1,%2,%3}, [%4];"
                 : "=r"(r0), "=r"(r1), "=r"(r2), "=r"(r3) : "r"(a));
}
__device__ __forceinline__ void ldsm2(unsigned& r0, unsigned& r1, unsigned a) {
    asm volatile("ldmatrix.sync.aligned.m8n8.x2.shared.b16 {%0,%1}, [%2];"
                 : "=r"(r0), "=r"(r1) : "r"(a));
}
__device__ __forceinline__ void mma16816(float* c, const unsigned* a,
                                         unsigned b0, unsigned b1) {
    asm volatile(
        "mma.sync.aligned.m16n8k16.row.col.f32.f16.f16.f32 "
        "{%0,%1,%2,%3}, {%4,%5,%6,%7}, {%8,%9}, {%0,%1,%2,%3};"
        : "+f"(c[0]), "+f"(c[1]), "+f"(c[2]), "+f"(c[3])
        : "r"(a[0]), "r"(a[1]), "r"(a[2]), "r"(a[3]), "r"(b0), "r"(b1));
}
__device__ __forceinline__ float wsel(int ln) {     // pooled node weight
    return (ln == 0) ? WROOT : ((ln & 3) == 0 ? 0.5f : 1.0f);
}
__device__ __forceinline__ float pick4(const float* v, int s) {
    return (s == 0) ? v[0] : (s == 1) ? v[1] : (s == 2) ? v[2] : v[3];
}
__device__ __forceinline__ int imin(int a, int b) { return a < b ? a : b; }
__device__ __forceinline__ int imax(int a, int b) { return a > b ? a : b; }

// ---- phase 2: MMA over 11 nt tiles + fused pooling, templated on half -----
template<int GH>
__device__ __forceinline__ void phase2(const unsigned (&ah)[4][2][4],
                                       unsigned bAddr, const float* t2r,
                                       int cp2, float (&v)[4][4]) {
    #pragma unroll
    for (int r = 0; r < 4; ++r)
        #pragma unroll
        for (int g = 0; g < 4; ++g) v[r][g] = 0.f;

    #pragma unroll
    for (int i = 0; i < 11; ++i) {
        const int nt = 10 * GH + i;
        float acc[8] = {0.f, 0.f, 0.f, 0.f, 0.f, 0.f, 0.f, 0.f};
        #pragma unroll
        for (int kk = 0; kk < 4; ++kk) {
            unsigned b0, b1;
            ldsm2(b0, b1, bAddr + nt * (8 * 144) + kk * 32);
            mma16816(acc,     ah[kk][0], b0, b1);
            mma16816(acc + 4, ah[kk][1], b0, b1);
        }
        // pooling for these 8 node-columns (compile-time graph mapping)
        const int n0c = 8 * nt;
        const int gl  = n0c / 21, gh2 = (n0c + 7) / 21;
        const int bnd = 21 * (gl + 1);
        const int Gl  = imin(imax(gl  - 4 * GH, 0), 3);
        const int Gh  = imin(imax(gh2 - 4 * GH, 0), 3);
        const int n0 = n0c + cp2, n1 = n0 + 1;
        const int l0 = n0 - ((n0 < bnd) ? 21 * gl : bnd);
        const int l1 = n1 - ((n1 < bnd) ? 21 * gl : bnd);
        float w0 = wsel(l0), w1 = wsel(l1);
        if (GH == 0 && nt == 10) {        // own cols < 84 only
            if (n0 >= 84) w0 = 0.f;
            if (n1 >= 84) w1 = 0.f;
        }
        if (GH == 1 && nt == 10) {        // own cols >= 84 only
            if (n0 < 84) w0 = 0.f;
            if (n1 < 84) w1 = 0.f;
        }
        #pragma unroll
        for (int r = 0; r < 4; ++r) {
            float q0 = fmaxf(acc[2 * r]     + t2r[r], 0.f) * w0;
            float q1 = fmaxf(acc[2 * r + 1] + t2r[r], 0.f) * w1;
            if (Gl == Gh) {
                v[r][Gl] += q0 + q1;
            } else {
                float qlo = ((n0 < bnd) ? q0 : 0.f) + ((n1 < bnd) ? q1 : 0.f);
                v[r][Gl] += qlo;
                v[r][Gh] += (q0 + q1) - qlo;
            }
        }
    }
}

// ---------------------------------------------------------------------------
__global__ void __launch_bounds__(256, 3)
gcn_t4_kernel(const float* __restrict__ x,
              const float* __restrict__ W1, const float* __restrict__ b1,
              const float* __restrict__ g1, const float* __restrict__ be1,
              const float* __restrict__ m1, const float* __restrict__ v1,
              const float* __restrict__ W2, const float* __restrict__ b2,
              const float* __restrict__ g2, const float* __restrict__ be2,
              const float* __restrict__ m2, const float* __restrict__ v2,
              const float* __restrict__ W3, const float* __restrict__ b3,
              float* __restrict__ out) {
    extern __shared__ char smc[];
    float* smf = (float*)smc;
    const unsigned sb = smem_u32(smc);
    const int tid  = threadIdx.x;
    const int lane = tid & 31;
    const int wid  = tid >> 5;          // 0..7
    const int jq   = wid & 3;           // j-strip of 32
    const int ghf  = wid >> 2;          // node half (graphs 4*ghf..4*ghf+3)

    // ---------------- staging (once per CTA) -------------------------------
    for (int i = tid; i < 8192; i += 256) {          // A = W2^T * diag(s2)
        int j = i & 127, k = i >> 7;
        float s = g2[j] * rsqrtf(v2[j] + 1e-5f);
        *(__half*)(smc + SB_AH + j * 144 + k * 2) =
            __float2half(W2[k * 128 + j] * s);
    }
    for (int i = tid; i < 4096; i += 256) {          // W3/21 padded [128][32]
        int j = i >> 5, c = i & 31;
        smf[SB_W3 / 4 + i] = (c < NCLS) ? W3[j * NCLS + c] * (1.f / 21.f) : 0.f;
    }
    if (tid < 128) {
        float s = g2[tid] * rsqrtf(v2[tid] + 1e-5f);
        smf[SB_T2 / 4 + tid] = (b2[tid] - m2[tid]) * s + be2[tid];
    }
    if (tid < NCLS) smf[SB_B3 / 4 + tid] = b3[tid];
    for (int i = tid; i < 192; i += 256) smf[SB_C / 4 + i] = W1[i];
    if (tid < 64) {
        float s = g1[tid] * rsqrtf(v1[tid] + 1e-5f);
        smf[SB_S1 / 4 + tid] = s;
        smf[SB_T1 / 4 + tid] = (b1[tid] - m1[tid]) * s + be1[tid];
    }
    __syncthreads();

    // ---- per-warp invariants ---------------------------------------------
    float t2r[4];
    #pragma unroll
    for (int r = 0; r < 4; ++r)
        t2r[r] = smf[SB_T2 / 4 + 32 * jq + (lane >> 2) + 8 * r];
    const unsigned bAddr = sb + SB_H + (lane & 7) * 144
                         + ((lane >> 3) & 1) * 16;
    const int cp2 = 2 * (lane & 3);

    // A fragments: static across all tiles -> load ONCE (32 regs)
    unsigned ah[4][2][4];
    #pragma unroll
    for (int kk = 0; kk < 4; ++kk)
        #pragma unroll
        for (int mt = 0; mt < 2; ++mt)
            ldsm4(ah[kk][mt][0], ah[kk][mt][1], ah[kk][mt][2], ah[kk][mt][3],
                  sb + SB_AH + (32 * jq + 16 * mt + (lane & 15)) * 144
                  + (lane >> 4) * 16 + kk * 32);

    for (int tile = blockIdx.x; tile < NTILES; tile += GRID) {
        const int gbase = tile * 8;

        // ---- phase 1: layer 1 + mix + BN + ReLU + mix2 -> H (warp=graph) --
        {
            const float2 w1a = ((const float2*)(smf + SB_C / 4))[lane];
            const float2 w1b = ((const float2*)(smf + SB_C / 4 + 64))[lane];
            const float2 w1c = ((const float2*)(smf + SB_C / 4 + 128))[lane];
            const float2 s1  = ((const float2*)(smf + SB_S1 / 4))[lane];
            const float2 t1  = ((const float2*)(smf + SB_T1 / 4))[lane];
            const float* xg = x + (size_t)(gbase + wid) * 63;
            const float xv0 = xg[lane];
            const float xv1 = (lane < 31) ? xg[32 + lane] : 0.f;

            float2 z0, h0;
            {
                float xa = __shfl_sync(0xffffffffu, xv0, 0);
                float xb = __shfl_sync(0xffffffffu, xv0, 1);
                float xc = __shfl_sync(0xffffffffu, xv0, 2);
                z0.x = fmaf(xa, w1a.x, fmaf(xb, w1b.x, xc * w1c.x));
                z0.y = fmaf(xa, w1a.y, fmaf(xb, w1b.y, xc * w1c.y));
                h0.x = fmaxf(fmaf(z0.x, s1.x, t1.x), 0.f);
                h0.y = fmaxf(fmaf(z0.y, s1.y, t1.y), 0.f);
                *(__half2*)(smc + SB_H + (21 * wid) * 144 + lane * 4) =
                    __floats2half2_rn(h0.x, h0.y);
            }
            #pragma unroll
            for (int f = 0; f < 5; ++f) {
                float2 zp = z0, hp = h0;
                #pragma unroll
                for (int i = 0; i < 4; ++i) {
                    const int n = 1 + 4 * f + i;
                    const float cp = (i == 0) ? R2C : 0.5f;
                    const int i0 = 3 * n;
                    float xa = (i0 < 32) ? __shfl_sync(0xffffffffu, xv0, i0)
                                         : __shfl_sync(0xffffffffu, xv1, i0 - 32);
                    float xb = (i0 + 1 < 32) ? __shfl_sync(0xffffffffu, xv0, i0 + 1)
                                             : __shfl_sync(0xffffffffu, xv1, i0 - 31);
                    float xc = (i0 + 2 < 32) ? __shfl_sync(0xffffffffu, xv0, i0 + 2)
                                             : __shfl_sync(0xffffffffu, xv1, i0 - 30);
                    float2 zn, hn;
                    zn.x = fmaf(xa, w1a.x, fmaf(xb, w1b.x, xc * w1c.x));
                    zn.y = fmaf(xa, w1a.y, fmaf(xb, w1b.y, xc * w1c.y));
                    float m1x = fmaf(0.5f, zn.x, cp * zp.x);
                    float m1y = fmaf(0.5f, zn.y, cp * zp.y);
                    hn.x = fmaxf(fmaf(m1x, s1.x, t1.x), 0.f);
                    hn.y = fmaxf(fmaf(m1y, s1.y, t1.y), 0.f);
                    float m2x = fmaf(0.5f, hn.x, cp * hp.x);
                    float m2y = fmaf(0.5f, hn.y, cp * hp.y);
                    *(__half2*)(smc + SB_H + (21 * wid + n) * 144 + lane * 4) =
                        __floats2half2_rn(m2x, m2y);
                    zp = zn; hp = hn;
                }
            }
        }
        __syncthreads();                              // BAR1: H ready

        // ---- phase 2+3: MMA (M=32, 11 nt) + fused pooling -----------------
        {
            float v[4][4];
            if (ghf == 0) phase2<0>(ah, bAddr, t2r, cp2, v);
            else          phase2<1>(ah, bAddr, t2r, cp2, v);

            #pragma unroll
            for (int r = 0; r < 4; ++r)
                #pragma unroll
                for (int g = 0; g < 4; ++g) {
                    v[r][g] += __shfl_xor_sync(0xffffffffu, v[r][g], 1);
                    v[r][g] += __shfl_xor_sync(0xffffffffu, v[r][g], 2);
                }
            const int gs = lane & 3;
            #pragma unroll
            for (int r = 0; r < 4; ++r) {
                const int j = 32 * jq + (lane >> 2) + 8 * r;
                smf[SB_PV / 4 + j * 8 + 4 * ghf + gs] = pick4(v[r], gs);
            }
        }
        __syncthreads();                              // BAR2: PV ready

        // ---- phase 4: layer 3 partial over j-strip ------------------------
        {
            float y[8];
            #pragma unroll
            for (int g = 0; g < 8; ++g) y[g] = 0.f;
            #pragma unroll
            for (int jj = 0; jj < 16; ++jj) {
                const int j = 16 * wid + jj;
                float wc = smf[SB_W3 / 4 + j * 32 + lane];
                float4 p0 = *(const float4*)(smf + SB_PV / 4 + j * 8);
                float4 p1 = *(const float4*)(smf + SB_PV / 4 + j * 8 + 4);
                y[0] = fmaf(p0.x, wc, y[0]); y[1] = fmaf(p0.y, wc, y[1]);
                y[2] = fmaf(p0.z, wc, y[2]); y[3] = fmaf(p0.w, wc, y[3]);
                y[4] = fmaf(p1.x, wc, y[4]); y[5] = fmaf(p1.y, wc, y[5]);
                y[6] = fmaf(p1.z, wc, y[6]); y[7] = fmaf(p1.w, wc, y[7]);
            }
            #pragma unroll
            for (int g = 0; g < 8; ++g)
                smf[SB_PY / 4 + wid * 256 + g * 32 + lane] = y[g];
        }
        __syncthreads();                              // BAR3: PY ready

        // ---- phase 5: combine + log_softmax (warp = graph) ----------------
        {
            float yy = 0.f;
            #pragma unroll
            for (int w = 0; w < 8; ++w)
                yy += smf[SB_PY / 4 + w * 256 + wid * 32 + lane];
            float logit = (lane < NCLS) ? yy + smf[SB_B3 / 4 + lane] : -1e30f;
            float mx = logit;
            #pragma unroll
            for (int o = 16; o; o >>= 1)
                mx = fmaxf(mx, __shfl_xor_sync(0xffffffffu, mx, o));
            float e = (lane < NCLS) ? expf(logit - mx) : 0.f;
            float s = e;
            #pragma unroll
            for (int o = 16; o; o >>= 1)
                s += __shfl_xor_sync(0xffffffffu, s, o);
            if (lane < NCLS)
                out[(size_t)(gbase + wid) * NCLS + lane] = logit - mx - logf(s);
        }
        // H/PV/PY cross-tile hazards all ordered by the BAR1..BAR3 chain
    }
}

extern "C" void kernel_launch(void* const* d_in, const int* in_sizes, int n_in,
                              void* d_out, int out_size) {
    const float* x   = (const float*)d_in[0];
    const float* W1  = (const float*)d_in[1];
    const float* b1  = (const float*)d_in[2];
    const float* g1  = (const float*)d_in[3];
    const float* be1 = (const float*)d_in[4];
    const float* m1  = (const float*)d_in[5];
    const float* v1  = (const float*)d_in[6];
    const float* W2  = (const float*)d_in[7];
    const float* b2  = (const float*)d_in[8];
    const float* g2  = (const float*)d_in[9];
    const float* be2 = (const float*)d_in[10];
    const float* m2  = (const float*)d_in[11];
    const float* v2  = (const float*)d_in[12];
    const float* W3  = (const float*)d_in[13];
    const float* b3  = (const float*)d_in[14];

    cudaFuncSetAttribute(gcn_t4_kernel,
                         cudaFuncAttributeMaxDynamicSharedMemorySize, SB_TOT);
    gcn_t4_kernel<<<GRID, 256, SB_TOT>>>(
        x, W1, b1, g1, be1, m1, v1,
        W2, b2, g2, be2, m2, v2, W3, b3, (float*)d_out);
}